// round 13
// baseline (speedup 1.0000x reference)
#include <cuda_runtime.h>
#include <cstdint>
#include <cstddef>

// ============================================================================
// Problem constants
// ============================================================================
#define K_ALPHA 0.01f

static constexpr int MT = 4096;   // rows (2*2048)
static constexpr int NT = 11008;  // output features
static constexpr int KT = 4096;   // reduction

static constexpr int BM = 128;
static constexpr int BN = 128;

// K split: per chunk, 96 int8-k (3 x mma k32) + 32 fp32-k (FFMA2). 32 chunks.
static constexpr int KINT  = 3072;
static constexpr int KFLT  = 1024;
static constexpr int KI_CH = 96;
static constexpr int KF_CH = 32;
static constexpr int NCH   = 32;

// stage layout (bytes, per stage)
static constexpr int OFF_AI = 0;          // int8 A: 128 rows x 128B (96 used, swizzled)
static constexpr int OFF_BI = 16384;      // int8 B: 128 rows x 128B
static constexpr int OFF_AT = 32768;      // fp32 A^T: 32 k-rows x 512B  [k][m]
static constexpr int OFF_BD = 49152;      // fp32 B dup: 128 c-rows x 256B [c][2k] swizzled
static constexpr int STAGE_BYTES = 81920; // 80KB
static constexpr int STAGES = 2;
static constexpr int SMEM_ALLOC = STAGES * STAGE_BYTES;  // 160KB

// scratch (device-global: allocation is forbidden)
__device__ __align__(16) signed char g_px[(size_t)MT * KT];        // 16.8 MB int8
__device__ __align__(16) signed char g_pw[(size_t)NT * KT];        // 45.1 MB int8
__device__ __align__(16) float       g_at[(size_t)KFLT * MT];      // 16.8 MB fp32 [k][m]
__device__ __align__(16) float       g_bd[(size_t)NT * KFLT * 2];  // 90.2 MB fp32 dup [c][2k]

// ============================================================================
// PTX helpers — sm_103 BASE target only
// ============================================================================
__device__ __forceinline__ unsigned smem_to_u32(const void* p) {
    unsigned a;
    asm("{ .reg .u64 t; cvta.to.shared.u64 t, %1; cvt.u32.u64 %0, t; }"
        : "=r"(a) : "l"(p));
    return a;
}
__device__ __forceinline__ void cp_async16(unsigned smem_addr, const void* gptr) {
    asm volatile("cp.async.cg.shared.global [%0], [%1], 16;"
                 :: "r"(smem_addr), "l"(gptr) : "memory");
}
__device__ __forceinline__ void cp_commit() {
    asm volatile("cp.async.commit_group;" ::: "memory");
}
template <int N>
__device__ __forceinline__ void cp_wait() {
    asm volatile("cp.async.wait_group %0;" :: "n"(N) : "memory");
}
__device__ __forceinline__ void ldsm_x4(unsigned (&r)[4], unsigned addr) {
    asm volatile("ldmatrix.sync.aligned.m8n8.x4.shared.b16 {%0,%1,%2,%3}, [%4];"
                 : "=r"(r[0]), "=r"(r[1]), "=r"(r[2]), "=r"(r[3]) : "r"(addr));
}
__device__ __forceinline__ void mma_s8(int (&c)[4], const unsigned (&a)[4],
                                       unsigned b0, unsigned b1) {
    asm volatile(
        "mma.sync.aligned.m16n8k32.row.col.s32.s8.s8.s32 "
        "{%0,%1,%2,%3}, {%4,%5,%6,%7}, {%8,%9}, {%0,%1,%2,%3};"
        : "+r"(c[0]), "+r"(c[1]), "+r"(c[2]), "+r"(c[3])
        : "r"(a[0]), "r"(a[1]), "r"(a[2]), "r"(a[3]), "r"(b0), "r"(b1));
}
__device__ __forceinline__ unsigned long long lds64(unsigned a) {
    unsigned long long v;
    asm volatile("ld.shared.b64 %0, [%1];" : "=l"(v) : "r"(a));
    return v;
}
__device__ __forceinline__ void lds128_2u64(unsigned long long& lo,
                                            unsigned long long& hi, unsigned a) {
    asm volatile("ld.shared.v2.u64 {%0,%1}, [%2];" : "=l"(lo), "=l"(hi) : "r"(a));
}
// packed fp32 dual-MAC (fma pipe)
__device__ __forceinline__ void ffma2(unsigned long long& d, unsigned long long a,
                                      unsigned long long b) {
    asm("fma.rn.f32x2 %0, %1, %2, %0;" : "+l"(d) : "l"(a), "l"(b));
}

// int8 smem: 128B padded rows, 16B slot swizzle (slot ^ (row&7)) -> LDSM conflict-free
__device__ __forceinline__ unsigned swi(unsigned base, int r, int c16) {
    return base + (unsigned)(r * 128) + (unsigned)(((c16 ^ (r & 7)) << 4));
}

// ============================================================================
// Pack kernels
// ============================================================================
__global__ void __launch_bounds__(256) pack_kernel(const int* __restrict__ src,
                                                   signed char* __restrict__ dst,
                                                   int n16) {
    int i = blockIdx.x * 256 + threadIdx.x;
    if (i >= n16) return;
    const int4* s = reinterpret_cast<const int4*>(src) + (size_t)i * 4;
    int4 a = s[0], b = s[1], c = s[2], d = s[3];
    int r0 = (a.x & 0xff) | ((a.y & 0xff) << 8) | ((a.z & 0xff) << 16) | ((a.w & 0xff) << 24);
    int r1 = (b.x & 0xff) | ((b.y & 0xff) << 8) | ((b.z & 0xff) << 16) | ((b.w & 0xff) << 24);
    int r2 = (c.x & 0xff) | ((c.y & 0xff) << 8) | ((c.z & 0xff) << 16) | ((c.w & 0xff) << 24);
    int r3 = (d.x & 0xff) | ((d.y & 0xff) << 8) | ((d.z & 0xff) << 16) | ((d.w & 0xff) << 24);
    reinterpret_cast<int4*>(dst)[i] = make_int4(r0, r1, r2, r3);
}

// A^T fp32: at[k][m] = (float)x[m][3072+k], tiled transpose
__global__ void __launch_bounds__(256) packAT_kernel(const int* __restrict__ x,
                                                     float* __restrict__ at) {
    __shared__ float tile[32][33];
    int kb = blockIdx.x * 32;   // 0..992
    int mb = blockIdx.y * 32;   // 0..4064
    int tx = threadIdx.x & 31;
    int ty = threadIdx.x >> 5;  // 0..7
#pragma unroll
    for (int i = 0; i < 32; i += 8)
        tile[ty + i][tx] = (float)x[(size_t)(mb + ty + i) * KT + (KINT + kb + tx)];
    __syncthreads();
#pragma unroll
    for (int i = 0; i < 32; i += 8)
        at[(size_t)(kb + ty + i) * MT + (mb + tx)] = tile[tx][ty + i];
}

// B dup fp32: bd[c][2k+{0,1}] = (float)w[c][3072+k]
__global__ void __launch_bounds__(256) packBD_kernel(const int* __restrict__ w,
                                                     float* __restrict__ bd, int n4) {
    int i = blockIdx.x * 256 + threadIdx.x;
    if (i >= n4) return;
    int c = i >> 8;               // KFLT/4 = 256 quads per row
    int q = i & 255;
    int4 v = reinterpret_cast<const int4*>(w + (size_t)c * KT + KINT)[q];
    float4 lo = make_float4((float)v.x, (float)v.x, (float)v.y, (float)v.y);
    float4 hi = make_float4((float)v.z, (float)v.z, (float)v.w, (float)v.w);
    float4* dst = reinterpret_cast<float4*>(bd + (size_t)c * (KFLT * 2) + (size_t)q * 8);
    dst[0] = lo;
    dst[1] = hi;
}

// ============================================================================
// GEMM: 128x128 tile/CTA. Per chunk: 96 int8-k (mma.sync, int pipe) overlapped
// with 32 fp32-k (FFMA2, fma pipe). 8 warps 4(M)x2(N); 64 int32 + 32 f32x2 acc.
// ============================================================================
__global__ void __launch_bounds__(256) gemm_kernel(const float* __restrict__ bias,
                                                   float* __restrict__ out) {
    extern __shared__ char smem[];
    unsigned smemU = smem_to_u32(smem);

    const int tid  = threadIdx.x;
    const int lane = tid & 31;
    const int wid  = tid >> 5;
    const int wm   = wid & 3;    // M warp (32 rows)
    const int wn   = wid >> 2;   // N warp (64 cols)
    const int m0   = blockIdx.y * BM;
    const int n0   = blockIdx.x * BN;

    // ---- loader mapping ----
    // int8: one thread per row (256 rows total), 6x16B swizzled
    const signed char* gI;
    unsigned dIbase;
    {
        int r = tid;
        if (r < 128) {
            gI = g_px + (size_t)(m0 + r) * KT;
            dIbase = OFF_AI + (unsigned)r * 128;
        } else {
            gI = g_pw + (size_t)(n0 + (r - 128)) * KT;
            dIbase = OFF_BI + (unsigned)(r - 128) * 128;
        }
    }
    const int r7 = (tid & 127) & 7;
    // fp32 A^T: thread -> k-row tid>>3, chunks (tid&7)+8j
    const int at_k = tid >> 3;
    const int at_c = tid & 7;
    const float* gAT = g_at + (size_t)at_k * MT + m0;
    // fp32 B dup: thread -> c-row tid>>1, 8 swizzled 16B chunks
    const int bd_c = tid >> 1;
    const int bd_h = tid & 1;
    const int bd_sx = (bd_c >> 3) & 7;
    const float* gBD = g_bd + (size_t)(n0 + bd_c) * (KFLT * 2);

    auto load_stage = [&](int t, int slot) {
        unsigned sb = smemU + (unsigned)slot * STAGE_BYTES;
        const signed char* si = gI + t * KI_CH;
#pragma unroll
        for (int c = 0; c < 6; ++c)
            cp_async16(sb + dIbase + (unsigned)((c ^ r7) << 4), si + c * 16);
        const char* sa = (const char*)gAT + (size_t)t * KF_CH * MT * 4;
        unsigned da = sb + OFF_AT + (unsigned)at_k * 512;
#pragma unroll
        for (int j = 0; j < 4; ++j)
            cp_async16(da + (unsigned)((at_c + 8 * j) << 4), sa + (at_c + 8 * j) * 16);
        const char* sbd = (const char*)gBD + (size_t)t * 256;
        unsigned db = sb + OFF_BD + (unsigned)bd_c * 256;
#pragma unroll
        for (int j = 0; j < 8; ++j) {
            int k2 = bd_h * 8 + j;
            int slot16 = (k2 & 8) | ((k2 & 7) ^ bd_sx);
            cp_async16(db + (unsigned)(slot16 << 4), sbd + k2 * 16);
        }
    };

    // ---- accumulators ----
    int acc[2][8][4];
#pragma unroll
    for (int mi = 0; mi < 2; ++mi)
#pragma unroll
        for (int ni = 0; ni < 8; ++ni)
#pragma unroll
            for (int j = 0; j < 4; ++j) acc[mi][ni][j] = 0;
    unsigned long long accF[4][8];
#pragma unroll
    for (int p = 0; p < 4; ++p)
#pragma unroll
        for (int j = 0; j < 8; ++j) accF[p][j] = 0ull;

    // int fragment lane bases (proven in R8/R9)
    const int frag_r = ((lane >> 3) & 1) * 8 + (lane & 7);
    const int frag_c = lane >> 4;
    // fp lane bases
    const int f_rb = wm * 32 + ((lane >> 3) << 1);   // row-pair base (even)
    const int f_cb = wn * 64 + (lane & 7) * 8;       // col base
    const int f_sx = lane & 7;

    load_stage(0, 0);
    cp_commit();

#pragma unroll 1
    for (int t = 0; t < NCH; ++t) {
        if (t > 0) __syncthreads();   // prior compute done before its buffer is reloaded
        if (t + 1 < NCH) {
            load_stage(t + 1, (t + 1) & 1);
            cp_commit();
            cp_wait<1>();
        } else {
            cp_wait<0>();
        }
        __syncthreads();              // chunk t visible

        unsigned sb = smemU + (unsigned)(t & 1) * STAGE_BYTES;
        unsigned aB = sb + OFF_AI;
        unsigned bB = sb + OFF_BI;

        // ===== int path: 3 x (m16n8k32 sweep) over 96 int8-k =====
#pragma unroll
        for (int ks = 0; ks < 3; ++ks) {
            const int cch = ks * 2 + frag_c;
            unsigned a[2][4];
#pragma unroll
            for (int mi = 0; mi < 2; ++mi) {
                int r = wm * 32 + mi * 16 + frag_r;
                ldsm_x4(a[mi], swi(aB, r, cch));
            }
#pragma unroll
            for (int np = 0; np < 4; ++np) {
                int r = wn * 64 + np * 16 + frag_r;
                unsigned q[4];
                ldsm_x4(q, swi(bB, r, cch));
                mma_s8(acc[0][2 * np],     a[0], q[0], q[2]);
                mma_s8(acc[1][2 * np],     a[1], q[0], q[2]);
                mma_s8(acc[0][2 * np + 1], a[0], q[1], q[3]);
                mma_s8(acc[1][2 * np + 1], a[1], q[1], q[3]);
            }
        }

        // ===== fp path: 32 k via FFMA2 (fma pipe) =====
        {
            const unsigned aTb = sb + OFF_AT + (unsigned)(f_rb * 4);
            const unsigned bDb = sb + OFF_BD + (unsigned)(f_cb * 256);
#pragma unroll
            for (int k2 = 0; k2 < 16; ++k2) {
                unsigned rowA = aTb + (unsigned)(2 * k2) * 512;
                unsigned long long a[4][2];
#pragma unroll
                for (int p = 0; p < 4; ++p) {
                    a[p][0] = lds64(rowA + p * 32);
                    a[p][1] = lds64(rowA + 512 + p * 32);
                }
                const int slot16 = (k2 & 8) | ((k2 & 7) ^ f_sx);
#pragma unroll
                for (int j = 0; j < 8; ++j) {
                    unsigned long long blo, bhi;
                    lds128_2u64(blo, bhi, bDb + (unsigned)(j * 256 + (slot16 << 4)));
#pragma unroll
                    for (int p = 0; p < 4; ++p) {
                        ffma2(accF[p][j], a[p][0], blo);
                        ffma2(accF[p][j], a[p][1], bhi);
                    }
                }
            }
        }
    }

    // ---- epilogue: exchange fp results via smem, combine, dequant+bias ----
    __syncthreads();
    // fpC col-major [c][r] fp32, 128x128 = 64KB at smem base
    {
        char* fp = smem;
#pragma unroll
        for (int j = 0; j < 8; ++j)
#pragma unroll
            for (int p = 0; p < 4; ++p) {
                int c = f_cb + j;
                int r = f_rb + 8 * p;  // even -> 8B aligned pair (r, r+1)
                *reinterpret_cast<unsigned long long*>(fp + (size_t)c * 512 + r * 4) =
                    accF[p][j];
            }
    }
    __syncthreads();

    const float* fpF = reinterpret_cast<const float*>(smem);
    const int row0 = m0 + wm * 32 + (lane >> 2);
    const int colb = n0 + wn * 64 + (lane & 3) * 2;
#pragma unroll
    for (int ni = 0; ni < 8; ++ni) {
        const int c  = colb + ni * 8;
        const int cl = c - n0;
        const float b0 = __ldg(bias + c);
        const float b1 = __ldg(bias + c + 1);
#pragma unroll
        for (int mi = 0; mi < 2; ++mi) {
            const int r  = row0 + mi * 16;
            const int rl = r - m0;
            float2 v0, v1;
            v0.x = K_ALPHA * ((float)acc[mi][ni][0] + fpF[cl * 128 + rl]) + b0;
            v0.y = K_ALPHA * ((float)acc[mi][ni][1] + fpF[(cl + 1) * 128 + rl]) + b1;
            v1.x = K_ALPHA * ((float)acc[mi][ni][2] + fpF[cl * 128 + rl + 8]) + b0;
            v1.y = K_ALPHA * ((float)acc[mi][ni][3] + fpF[(cl + 1) * 128 + rl + 8]) + b1;
            *reinterpret_cast<float2*>(out + (size_t)r * NT + c)       = v0;
            *reinterpret_cast<float2*>(out + (size_t)(r + 8) * NT + c) = v1;
        }
    }
}

// ============================================================================
// Launch
// ============================================================================
extern "C" void kernel_launch(void* const* d_in, const int* in_sizes, int n_in,
                              void* d_out, int out_size) {
    const int*   x    = (const int*)d_in[0];     // [2,2048,4096] int8-in-int32
    const int*   w    = (const int*)d_in[1];     // [11008,4096]  int8-in-int32
    const float* bias = (const float*)d_in[2];   // [1,11008]
    float*       out  = (float*)d_out;           // [4096,11008]

    void *px = nullptr, *pw = nullptr, *pat = nullptr, *pbd = nullptr;
    cudaGetSymbolAddress(&px, g_px);
    cudaGetSymbolAddress(&pw, g_pw);
    cudaGetSymbolAddress(&pat, g_at);
    cudaGetSymbolAddress(&pbd, g_bd);

    int nx16 = (MT * KT) / 16;
    int nw16 = (NT * KT) / 16;
    pack_kernel<<<(nx16 + 255) / 256, 256>>>(x, (signed char*)px, nx16);
    pack_kernel<<<(nw16 + 255) / 256, 256>>>(w, (signed char*)pw, nw16);
    packAT_kernel<<<dim3(KFLT / 32, MT / 32), 256>>>(x, (float*)pat);
    int n4 = NT * (KFLT / 4);
    packBD_kernel<<<(n4 + 255) / 256, 256>>>(w, (float*)pbd, n4);

    cudaFuncSetAttribute(gemm_kernel, cudaFuncAttributeMaxDynamicSharedMemorySize,
                         SMEM_ALLOC);
    gemm_kernel<<<dim3(NT / BN, MT / BM), 256, SMEM_ALLOC>>>(bias, out);
}

// round 15
// speedup vs baseline: 1.4149x; 1.4149x over previous
#include <cuda_runtime.h>
#include <cstdint>
#include <cstddef>

// ============================================================================
// Problem constants
// ============================================================================
#define K_ALPHA 0.01f

static constexpr int MT = 4096;   // rows (2*2048)
static constexpr int NT = 11008;  // output features
static constexpr int KT = 4096;   // reduction

static constexpr int BM = 128;
static constexpr int BN = 128;
static constexpr int BK = 128;              // K bytes per pipeline chunk
static constexpr int KCHUNKS = KT / BK;     // 32
static constexpr int STAGES = 3;

static constexpr int A_STAGE = BM * BK;     // 16384
static constexpr int B_STAGE = BN * BK;     // 16384
static constexpr int STAGE_BYTES = A_STAGE + B_STAGE;      // 32768
static constexpr int SMEM_ALLOC = STAGES * STAGE_BYTES;    // 98304 (2 CTAs/SM)

// int8 scratch (device-global: allocation is forbidden)
__device__ __align__(16) signed char g_px[(size_t)MT * KT];  // 16.8 MB
__device__ __align__(16) signed char g_pw[(size_t)NT * KT];  // 45.1 MB

// ============================================================================
// PTX helpers — sm_103 BASE target only (no 'a'-suffix features!)
// ============================================================================
__device__ __forceinline__ unsigned smem_to_u32(const void* p) {
    unsigned a;
    asm("{ .reg .u64 t; cvta.to.shared.u64 t, %1; cvt.u32.u64 %0, t; }"
        : "=r"(a) : "l"(p));
    return a;
}
__device__ __forceinline__ void cp_async16(unsigned smem_addr, const void* gptr) {
    asm volatile("cp.async.cg.shared.global [%0], [%1], 16;"
                 :: "r"(smem_addr), "l"(gptr) : "memory");
}
__device__ __forceinline__ void cp_commit() {
    asm volatile("cp.async.commit_group;" ::: "memory");
}
template <int N>
__device__ __forceinline__ void cp_wait() {
    asm volatile("cp.async.wait_group %0;" :: "n"(N) : "memory");
}
__device__ __forceinline__ void ldsm_x4(unsigned (&r)[4], unsigned addr) {
    asm volatile("ldmatrix.sync.aligned.m8n8.x4.shared.b16 {%0,%1,%2,%3}, [%4];"
                 : "=r"(r[0]), "=r"(r[1]), "=r"(r[2]), "=r"(r[3]) : "r"(addr));
}
__device__ __forceinline__ void mma_s8(int (&c)[4], const unsigned (&a)[4],
                                       unsigned b0, unsigned b1) {
    asm volatile(
        "mma.sync.aligned.m16n8k32.row.col.s32.s8.s8.s32 "
        "{%0,%1,%2,%3}, {%4,%5,%6,%7}, {%8,%9}, {%0,%1,%2,%3};"
        : "+r"(c[0]), "+r"(c[1]), "+r"(c[2]), "+r"(c[3])
        : "r"(a[0]), "r"(a[1]), "r"(a[2]), "r"(a[3]), "r"(b0), "r"(b1));
}

// smem tile: 128B rows, 8 x 16B slots, slot ^= (row & 7).
// 8 consecutive rows at a fixed logical slot hit 8 distinct 16B bank groups
// -> conflict-free LDSM and conflict-free STS from the cp.async pattern.
__device__ __forceinline__ unsigned swi(unsigned base, int r, int c16) {
    return base + (unsigned)(r * 128) + (unsigned)(((c16 ^ (r & 7)) << 4));
}

// ============================================================================
// Pack: int32 containers -> dense int8 (16 values per thread)
// ============================================================================
__global__ void __launch_bounds__(256) pack_kernel(const int* __restrict__ src,
                                                   signed char* __restrict__ dst,
                                                   int n16) {
    int i = blockIdx.x * 256 + threadIdx.x;
    if (i >= n16) return;
    const int4* s = reinterpret_cast<const int4*>(src) + (size_t)i * 4;
    int4 a = s[0], b = s[1], c = s[2], d = s[3];
    int r0 = (a.x & 0xff) | ((a.y & 0xff) << 8) | ((a.z & 0xff) << 16) | ((a.w & 0xff) << 24);
    int r1 = (b.x & 0xff) | ((b.y & 0xff) << 8) | ((b.z & 0xff) << 16) | ((b.w & 0xff) << 24);
    int r2 = (c.x & 0xff) | ((c.y & 0xff) << 8) | ((c.z & 0xff) << 16) | ((c.w & 0xff) << 24);
    int r3 = (d.x & 0xff) | ((d.y & 0xff) << 8) | ((d.z & 0xff) << 16) | ((d.w & 0xff) << 24);
    reinterpret_cast<int4*>(dst)[i] = make_int4(r0, r1, r2, r3);
}

// ============================================================================
// GEMM: 128x128 tile / CTA, mma.sync m16n8k32 s8, 3-stage x 128B-K cp.async
// pipeline, ONE __syncthreads per K-chunk. 8 warps as 4(M) x 2(N); warp tile
// 32x64; per-thread accum 2x8x4 = 64 s32. 2 CTAs/SM.
// ============================================================================
__global__ void __launch_bounds__(256, 2) gemm_kernel(const float* __restrict__ bias,
                                                      float* __restrict__ out) {
    extern __shared__ char smem[];
    unsigned smemU = smem_to_u32(smem);

    const int tid  = threadIdx.x;
    const int lane = tid & 31;
    const int wid  = tid >> 5;
    const int wm   = wid & 3;   // 0..3  (M direction, 32 rows each)
    const int wn   = wid >> 2;  // 0..1  (N direction, 64 cols each)
    const int m0   = blockIdx.y * BM;
    const int n0   = blockIdx.x * BN;

    // ---- loader mapping: one thread per tile row (128 A rows + 128 B rows),
    //      8 x 16B swizzled chunks per row per K-chunk.
    const signed char* gR;
    unsigned dRow;
    {
        if (tid < 128) {
            gR   = g_px + (size_t)(m0 + tid) * KT;
            dRow = (unsigned)tid * 128;                 // within A region
        } else {
            gR   = g_pw + (size_t)(n0 + (tid - 128)) * KT;
            dRow = A_STAGE + (unsigned)(tid - 128) * 128;  // within B region
        }
    }
    const int r7 = tid & 7;

    auto load_stage = [&](int t, int slot) {
        unsigned sb = smemU + (unsigned)slot * STAGE_BYTES + dRow;
        const signed char* src = gR + t * BK;
#pragma unroll
        for (int c = 0; c < 8; ++c)
            cp_async16(sb + (unsigned)((c ^ r7) << 4), src + c * 16);
    };

    // ---- prologue: fill 2 of 3 slots
    load_stage(0, 0); cp_commit();
    load_stage(1, 1); cp_commit();

    int acc[2][8][4];
#pragma unroll
    for (int mi = 0; mi < 2; ++mi)
#pragma unroll
        for (int ni = 0; ni < 8; ++ni)
#pragma unroll
            for (int j = 0; j < 4; ++j) acc[mi][ni][j] = 0;

    // fragment lane bases (layout proven in R8)
    const int frag_r = ((lane >> 3) & 1) * 8 + (lane & 7);  // row within 16-row group
    const int frag_c = lane >> 4;                            // 16B half of a k32 slice

#pragma unroll 1
    for (int t = 0; t < KCHUNKS; ++t) {
        cp_wait<1>();        // chunk t's group complete
        __syncthreads();     // data visible to all; everyone done with chunk t-1

        if (t + 2 < KCHUNKS) load_stage(t + 2, (t + 2) % STAGES);
        cp_commit();         // keep group accounting uniform (empty group ok)

        const unsigned aB = smemU + (unsigned)(t % STAGES) * STAGE_BYTES;
        const unsigned bB = aB + A_STAGE;

#pragma unroll
        for (int ks = 0; ks < 4; ++ks) {   // 4 x k32 slices per 128B chunk
            const int cch = 2 * ks + frag_c;
            unsigned a[2][4];
#pragma unroll
            for (int mi = 0; mi < 2; ++mi) {
                int r = wm * 32 + mi * 16 + frag_r;
                ldsm_x4(a[mi], swi(aB, r, cch));
            }
#pragma unroll
            for (int np = 0; np < 4; ++np) {
                int r = wn * 64 + np * 16 + frag_r;
                unsigned q[4];
                ldsm_x4(q, swi(bB, r, cch));
                mma_s8(acc[0][2 * np],     a[0], q[0], q[2]);
                mma_s8(acc[1][2 * np],     a[1], q[0], q[2]);
                mma_s8(acc[0][2 * np + 1], a[0], q[1], q[3]);
                mma_s8(acc[1][2 * np + 1], a[1], q[1], q[3]);
            }
        }
    }

    // ---- epilogue: dequant + bias, float2 stores (each 32B-sector aligned)
    const int row0 = m0 + wm * 32 + (lane >> 2);
    const int colb = n0 + wn * 64 + (lane & 3) * 2;
#pragma unroll
    for (int ni = 0; ni < 8; ++ni) {
        const int c = colb + ni * 8;
        const float b0 = __ldg(bias + c);
        const float b1 = __ldg(bias + c + 1);
#pragma unroll
        for (int mi = 0; mi < 2; ++mi) {
            const int r = row0 + mi * 16;
            float2 v0, v1;
            v0.x = K_ALPHA * (float)acc[mi][ni][0] + b0;
            v0.y = K_ALPHA * (float)acc[mi][ni][1] + b1;
            v1.x = K_ALPHA * (float)acc[mi][ni][2] + b0;
            v1.y = K_ALPHA * (float)acc[mi][ni][3] + b1;
            *reinterpret_cast<float2*>(out + (size_t)r * NT + c)       = v0;
            *reinterpret_cast<float2*>(out + (size_t)(r + 8) * NT + c) = v1;
        }
    }
}

// ============================================================================
// Launch
// ============================================================================
extern "C" void kernel_launch(void* const* d_in, const int* in_sizes, int n_in,
                              void* d_out, int out_size) {
    const int*   x    = (const int*)d_in[0];     // [2,2048,4096] int8-in-int32
    const int*   w    = (const int*)d_in[1];     // [11008,4096]  int8-in-int32
    const float* bias = (const float*)d_in[2];   // [1,11008]
    float*       out  = (float*)d_out;           // [4096,11008]

    void *px = nullptr, *pw = nullptr;
    cudaGetSymbolAddress(&px, g_px);
    cudaGetSymbolAddress(&pw, g_pw);

    int nx16 = (MT * KT) / 16;   // 1,048,576
    int nw16 = (NT * KT) / 16;   // 2,818,048
    pack_kernel<<<(nx16 + 255) / 256, 256>>>(x, (signed char*)px, nx16);
    pack_kernel<<<(nw16 + 255) / 256, 256>>>(w, (signed char*)pw, nw16);

    cudaFuncSetAttribute(gemm_kernel, cudaFuncAttributeMaxDynamicSharedMemorySize,
                         SMEM_ALLOC);
    gemm_kernel<<<dim3(NT / BN, MT / BM), 256, SMEM_ALLOC>>>(bias, out);
}

// round 16
// speedup vs baseline: 1.6774x; 1.1855x over previous
#include <cuda_runtime.h>
#include <cstdint>
#include <cstddef>

// ============================================================================
// Problem constants
// ============================================================================
#define K_ALPHA 0.01f

static constexpr int MT = 4096;   // rows (2*2048)
static constexpr int NT = 11008;  // output features
static constexpr int KT = 4096;   // reduction

static constexpr int BM = 128;
static constexpr int BN = 64;               // halved: 5504 CTAs / 296 slots = 18.59
static constexpr int BK = 64;               // K bytes per pipeline chunk
static constexpr int KCHUNKS = KT / BK;     // 64
static constexpr int STAGES = 6;

static constexpr int A_STAGE = BM * BK;     // 8192
static constexpr int B_STAGE = BN * BK;     // 4096
static constexpr int STAGE_BYTES = A_STAGE + B_STAGE;      // 12288
static constexpr int SMEM_ALLOC = STAGES * STAGE_BYTES;    // 73728 (2 CTAs/SM)

// int8 scratch (device-global: allocation is forbidden)
__device__ __align__(16) signed char g_px[(size_t)MT * KT];  // 16.8 MB
__device__ __align__(16) signed char g_pw[(size_t)NT * KT];  // 45.1 MB

// ============================================================================
// PTX helpers — sm_103 BASE target only (no 'a'-suffix features!)
// ============================================================================
__device__ __forceinline__ unsigned smem_to_u32(const void* p) {
    unsigned a;
    asm("{ .reg .u64 t; cvta.to.shared.u64 t, %1; cvt.u32.u64 %0, t; }"
        : "=r"(a) : "l"(p));
    return a;
}
__device__ __forceinline__ void cp_async16(unsigned smem_addr, const void* gptr) {
    asm volatile("cp.async.cg.shared.global [%0], [%1], 16;"
                 :: "r"(smem_addr), "l"(gptr) : "memory");
}
__device__ __forceinline__ void cp_commit() {
    asm volatile("cp.async.commit_group;" ::: "memory");
}
template <int N>
__device__ __forceinline__ void cp_wait() {
    asm volatile("cp.async.wait_group %0;" :: "n"(N) : "memory");
}
__device__ __forceinline__ void ldsm_x4(unsigned (&r)[4], unsigned addr) {
    asm volatile("ldmatrix.sync.aligned.m8n8.x4.shared.b16 {%0,%1,%2,%3}, [%4];"
                 : "=r"(r[0]), "=r"(r[1]), "=r"(r[2]), "=r"(r[3]) : "r"(addr));
}
__device__ __forceinline__ void mma_s8(int (&c)[4], const unsigned (&a)[4],
                                       unsigned b0, unsigned b1) {
    asm volatile(
        "mma.sync.aligned.m16n8k32.row.col.s32.s8.s8.s32 "
        "{%0,%1,%2,%3}, {%4,%5,%6,%7}, {%8,%9}, {%0,%1,%2,%3};"
        : "+r"(c[0]), "+r"(c[1]), "+r"(c[2]), "+r"(c[3])
        : "r"(a[0]), "r"(a[1]), "r"(a[2]), "r"(a[3]), "r"(b0), "r"(b1));
}

// Swizzled smem address: rows of 64B, 4x16B slots, slot ^= (row>>1)&3.
// 8 consecutive rows at a fixed logical slot hit 8 distinct 16B groups mod
// 128B -> conflict-free LDSM (proven in R8).
__device__ __forceinline__ unsigned sw_off(int r, int c) {
    return (unsigned)(r * 64) + (unsigned)(((c ^ ((r >> 1) & 3)) << 4));
}

// ============================================================================
// Pack: int32 containers -> dense int8 (16 values per thread)
// ============================================================================
__global__ void __launch_bounds__(256) pack_kernel(const int* __restrict__ src,
                                                   signed char* __restrict__ dst,
                                                   int n16) {
    int i = blockIdx.x * 256 + threadIdx.x;
    if (i >= n16) return;
    const int4* s = reinterpret_cast<const int4*>(src) + (size_t)i * 4;
    int4 a = s[0], b = s[1], c = s[2], d = s[3];
    int r0 = (a.x & 0xff) | ((a.y & 0xff) << 8) | ((a.z & 0xff) << 16) | ((a.w & 0xff) << 24);
    int r1 = (b.x & 0xff) | ((b.y & 0xff) << 8) | ((b.z & 0xff) << 16) | ((b.w & 0xff) << 24);
    int r2 = (c.x & 0xff) | ((c.y & 0xff) << 8) | ((c.z & 0xff) << 16) | ((c.w & 0xff) << 24);
    int r3 = (d.x & 0xff) | ((d.y & 0xff) << 8) | ((d.z & 0xff) << 16) | ((d.w & 0xff) << 24);
    reinterpret_cast<int4*>(dst)[i] = make_int4(r0, r1, r2, r3);
}

// ============================================================================
// GEMM: 128x64 tile / CTA, mma.sync m16n8k32 s8, 6-stage cp.async pipeline
// (R8-proven structure). 8 warps as 4(M) x 2(N); warp tile 32x32; per-thread
// accum 2x4x4 = 32 s32. 2 CTAs/SM; 5504 CTAs -> 19 waves (2.2% quantization).
// ============================================================================
__global__ void __launch_bounds__(256, 2) gemm_kernel(const float* __restrict__ bias,
                                                      float* __restrict__ out) {
    extern __shared__ char smem[];
    unsigned smemU = smem_to_u32(smem);

    const int tid  = threadIdx.x;
    const int lane = tid & 31;
    const int wid  = tid >> 5;
    const int wm   = wid & 3;   // 0..3  (M direction, 32 rows each)
    const int wn   = wid >> 2;  // 0..1  (N direction, 32 cols each)
    const int m0   = blockIdx.y * BM;
    const int n0   = blockIdx.x * BN;

    // ---- loader mapping: 192 rows x 4 slots = 768 16B-chunks per stage,
    //      256 threads x 3 chunks: chunk ids tid, tid+256, tid+512.
    const signed char* gsrc[3];
    unsigned           sdst[3];
#pragma unroll
    for (int j = 0; j < 3; ++j) {
        int c    = tid + j * 256;
        int row  = c >> 2;
        int slot = c & 3;
        if (row < 128) {
            gsrc[j] = g_px + (size_t)(m0 + row) * KT + slot * 16;
            sdst[j] = sw_off(row, slot);                    // within A region
        } else {
            gsrc[j] = g_pw + (size_t)(n0 + (row - 128)) * KT + slot * 16;
            sdst[j] = A_STAGE + sw_off(row - 128, slot);    // within B region
        }
    }

    auto load_stage = [&](int t, int slot) {
        unsigned sb = smemU + (unsigned)slot * STAGE_BYTES;
        int ko = t * BK;
#pragma unroll
        for (int j = 0; j < 3; ++j)
            cp_async16(sb + sdst[j], gsrc[j] + ko);
    };

    // ---- prologue: fill STAGES-1 slots
#pragma unroll
    for (int s = 0; s < STAGES - 1; ++s) { load_stage(s, s); cp_commit(); }

    int acc[2][4][4];
#pragma unroll
    for (int mi = 0; mi < 2; ++mi)
#pragma unroll
        for (int ni = 0; ni < 4; ++ni)
#pragma unroll
            for (int j = 0; j < 4; ++j) acc[mi][ni][j] = 0;

    // fragment lane bases (layout proven in R8)
    const int frag_r = ((lane >> 3) & 1) * 8 + (lane & 7);  // row within 16-row group
    const int frag_c = lane >> 4;                            // 16B half of a k32 slice

#pragma unroll 1
    for (int t = 0; t < KCHUNKS; ++t) {
        cp_wait<STAGES - 2>();
        __syncthreads();

        if (t + STAGES - 1 < KCHUNKS) load_stage(t + STAGES - 1, (t + STAGES - 1) % STAGES);
        cp_commit();

        const unsigned aB = smemU + (unsigned)(t % STAGES) * STAGE_BYTES;
        const unsigned bB = aB + A_STAGE;

#pragma unroll
        for (int ks = 0; ks < 2; ++ks) {
            const int cch = 2 * ks + frag_c;
            unsigned a[2][4];
#pragma unroll
            for (int mi = 0; mi < 2; ++mi) {
                int r = wm * 32 + mi * 16 + frag_r;
                ldsm_x4(a[mi], aB + sw_off(r, cch));
            }
#pragma unroll
            for (int np = 0; np < 2; ++np) {
                int r = wn * 32 + np * 16 + frag_r;
                unsigned q[4];
                ldsm_x4(q, bB + sw_off(r, cch));
                mma_s8(acc[0][2 * np],     a[0], q[0], q[2]);
                mma_s8(acc[1][2 * np],     a[1], q[0], q[2]);
                mma_s8(acc[0][2 * np + 1], a[0], q[1], q[3]);
                mma_s8(acc[1][2 * np + 1], a[1], q[1], q[3]);
            }
        }
    }

    // ---- epilogue: dequant + bias, float2 stores (each 32B-sector aligned)
    const int row0 = m0 + wm * 32 + (lane >> 2);
    const int colb = n0 + wn * 32 + (lane & 3) * 2;
#pragma unroll
    for (int ni = 0; ni < 4; ++ni) {
        const int c = colb + ni * 8;
        const float b0 = __ldg(bias + c);
        const float b1 = __ldg(bias + c + 1);
#pragma unroll
        for (int mi = 0; mi < 2; ++mi) {
            const int r = row0 + mi * 16;
            float2 v0, v1;
            v0.x = K_ALPHA * (float)acc[mi][ni][0] + b0;
            v0.y = K_ALPHA * (float)acc[mi][ni][1] + b1;
            v1.x = K_ALPHA * (float)acc[mi][ni][2] + b0;
            v1.y = K_ALPHA * (float)acc[mi][ni][3] + b1;
            *reinterpret_cast<float2*>(out + (size_t)r * NT + c)       = v0;
            *reinterpret_cast<float2*>(out + (size_t)(r + 8) * NT + c) = v1;
        }
    }
}

// ============================================================================
// Launch
// ============================================================================
extern "C" void kernel_launch(void* const* d_in, const int* in_sizes, int n_in,
                              void* d_out, int out_size) {
    const int*   x    = (const int*)d_in[0];     // [2,2048,4096] int8-in-int32
    const int*   w    = (const int*)d_in[1];     // [11008,4096]  int8-in-int32
    const float* bias = (const float*)d_in[2];   // [1,11008]
    float*       out  = (float*)d_out;           // [4096,11008]

    void *px = nullptr, *pw = nullptr;
    cudaGetSymbolAddress(&px, g_px);
    cudaGetSymbolAddress(&pw, g_pw);

    int nx16 = (MT * KT) / 16;   // 1,048,576
    int nw16 = (NT * KT) / 16;   // 2,818,048
    pack_kernel<<<(nx16 + 255) / 256, 256>>>(x, (signed char*)px, nx16);
    pack_kernel<<<(nw16 + 255) / 256, 256>>>(w, (signed char*)pw, nw16);

    cudaFuncSetAttribute(gemm_kernel, cudaFuncAttributeMaxDynamicSharedMemorySize,
                         SMEM_ALLOC);
    gemm_kernel<<<dim3(NT / BN, MT / BM), 256, SMEM_ALLOC>>>(bias, out);
}